// round 1
// baseline (speedup 1.0000x reference)
#include <cuda_runtime.h>

// EKVNonLinearConv: out[b,co,y,x] = R*scale * sum_l clip(ALPHA*(sp1^2 - sp2^2), 0)
//   l = ci*9 + ky*3 + kx ; vg = xpad[b,ci,y+ky,x+kx] ; th = clip(theta[co,l],1,8)
//   a  = clip((vg-th)/denom, -50, 20), a2 = clip((vg-th-VD)/denom, -50, 20)
//   sp = log1p(exp(a)) ; denom = 2*N_EKV*VT = 0.075 ; VD=0.1 ; ALPHA=0.05625 ; R=0.1

#define CIN    16
#define COUTT  64
#define HH     32
#define WW     32
#define BB     8
#define CG     8      // couts per block
#define RPB    4      // output rows per block
#define NTHR   128    // 4 warps, one output row per warp
#define LPC    144    // CIN*3*3

__device__ __forceinline__ float ekv_term(float vg, float th) {
    const float INVD  = 13.3333333333f;   // 1/0.075
    const float DELTA = 1.3333333333f;    // 0.1/0.075
    float a  = (vg - th) * INVD;
    float a1 = fminf(a, 20.0f);
    a1 = fmaxf(a1, -50.0f);
    float a2 = fminf(a - DELTA, 20.0f);
    a2 = fmaxf(a2, -50.0f);
    float e1 = __expf(a1);
    float e2 = __expf(a2);
    float l1 = __logf(1.0f + e1);
    float l2 = __logf(1.0f + e2);
    // l1 >= l2 always (monotone), so clip(...,0) is a no-op.
    return fmaf(l1, l1, -l2 * l2);
}

__global__ __launch_bounds__(NTHR)
void ekv_conv_kernel(const float* __restrict__ x,
                     const float* __restrict__ theta,
                     const float* __restrict__ scale,
                     float* __restrict__ out)
{
    __shared__ float sx[CIN][RPB + 2][34];   // halo tile, rows y0-1..y0+4, cols -1..32
    __shared__ float sth[CG][LPC];           // clipped theta for this cout group
    __shared__ float srm[CIN][RPB + 2];      // per-(ci,row) max of sx row (skip threshold)

    const int rt = blockIdx.x;       // row tile 0..7
    const int cg = blockIdx.y;       // cout group 0..7
    const int b  = blockIdx.z;       // batch
    const int y0 = rt * RPB;
    const int c0 = cg * CG;
    const int tid = threadIdx.x;

    // ---- load x halo tile (zero-padded) ----
    for (int i = tid; i < CIN * (RPB + 2) * 34; i += NTHR) {
        int cc = i % 34;
        int r  = (i / 34) % (RPB + 2);
        int ci = i / (34 * (RPB + 2));
        int gy = y0 - 1 + r;
        int gx = cc - 1;
        float v = 0.0f;
        if (gy >= 0 && gy < HH && gx >= 0 && gx < WW)
            v = x[((b * CIN + ci) * HH + gy) * WW + gx];
        sx[ci][r][cc] = v;
    }
    // ---- load + clip theta for this cout group ----
    for (int i = tid; i < CG * LPC; i += NTHR) {
        int l = i % LPC;
        int c = i / LPC;
        float t = theta[(c0 + c) * LPC + l];
        sth[c][l] = fminf(fmaxf(t, 1.0f), 8.0f);
    }
    __syncthreads();

    // ---- per-(ci,row) max over the 34-wide row (conservative skip bound) ----
    if (tid < CIN * (RPB + 2)) {
        int r  = tid % (RPB + 2);
        int ci = tid / (RPB + 2);
        float m = -1e30f;
        #pragma unroll
        for (int cc = 0; cc < 34; cc++) m = fmaxf(m, sx[ci][r][cc]);
        srm[ci][r] = m;
    }
    __syncthreads();

    const int tx = tid & 31;    // output column
    const int ty = tid >> 5;    // output row within tile (warp id)

    float acc[CG];
    #pragma unroll
    for (int c = 0; c < CG; c++) acc[c] = 0.0f;

    // skip margin: terms with (vg - th) < -DSKIP have sp^2 < 5e-10 -> negligible
    const float DSKIP = 0.75f;

    #pragma unroll 1
    for (int ci = 0; ci < CIN; ci++) {
        #pragma unroll 1
        for (int ky = 0; ky < 3; ky++) {
            // warp-uniform threshold (same row for all lanes of this warp)
            const float vthr = srm[ci][ty + ky] + DSKIP;
            const float vg0 = sx[ci][ty + ky][tx + 0];
            const float vg1 = sx[ci][ty + ky][tx + 1];
            const float vg2 = sx[ci][ty + ky][tx + 2];
            const int lbase = ci * 9 + ky * 3;
            #pragma unroll
            for (int c = 0; c < CG; c++) {
                float th0 = sth[c][lbase + 0];
                float th1 = sth[c][lbase + 1];
                float th2 = sth[c][lbase + 2];
                // warp-uniform branches: th* and vthr identical across lanes
                if (th0 <= vthr) acc[c] += ekv_term(vg0, th0);
                if (th1 <= vthr) acc[c] += ekv_term(vg1, th1);
                if (th2 <= vthr) acc[c] += ekv_term(vg2, th2);
            }
        }
    }

    // fold ALPHA * R * scale into one epilogue multiply
    const float sc = scale[0] * (0.05625f * 0.1f);
    const int y = y0 + ty;
    #pragma unroll
    for (int c = 0; c < CG; c++) {
        out[((b * COUTT + (c0 + c)) * HH + y) * WW + tx] = acc[c] * sc;
    }
}

extern "C" void kernel_launch(void* const* d_in, const int* in_sizes, int n_in,
                              void* d_out, int out_size) {
    const float* x     = (const float*)d_in[0];
    const float* theta = (const float*)d_in[1];
    const float* scale = (const float*)d_in[2];
    float* out = (float*)d_out;
    (void)in_sizes; (void)n_in; (void)out_size;

    dim3 grid(HH / RPB, COUTT / CG, BB);   // 8 x 8 x 8 = 512 blocks
    dim3 block(NTHR);
    ekv_conv_kernel<<<grid, block>>>(x, theta, scale, out);
}

// round 2
// speedup vs baseline: 1.4864x; 1.4864x over previous
#include <cuda_runtime.h>

// EKVNonLinearConv via 1-D piecewise-linear table of f(d) = sp(min(a,20))^2 - sp(min(a-D,20))^2
//   a = d/0.075, D = 0.1/0.075. f == 0 exactly for d >= 1.6; f < 4e-10 for d < -0.9.
//   out = ALPHA*R*scale * sum_l f(vg - th)

#define CIN    16
#define COUTT  64
#define HH     32
#define WW     32
#define BB     8
#define CG     4      // couts per block
#define RPB    4      // output rows per block
#define NTHR   128    // 4 warps, one output row per warp
#define LPC    144    // CIN*3*3

#define TABN   1000
#define TD0    (-0.9f)
#define TD1    (1.6f)
#define TH     0.0025f          // (TD1-TD0)/TABN ; kink d=1.5 -> entry 960 (exact)
#define TINVH  400.0f

__device__ __forceinline__ float ekv_exact(float d) {
    // exact reference formula (used only for table build; accurate expf/log1pf)
    const float INVD  = 13.333333333333334f;
    const float DELTA = 1.3333333333333333f;
    float a  = d * INVD;
    float a1 = fminf(fmaxf(a, -50.0f), 20.0f);
    float a2 = fminf(fmaxf(a - DELTA, -50.0f), 20.0f);
    float l1 = log1pf(expf(a1));
    float l2 = log1pf(expf(a2));
    return fmaf(l1, l1, -l2 * l2);
}

__global__ __launch_bounds__(NTHR)
void ekv_conv_kernel(const float* __restrict__ x,
                     const float* __restrict__ theta,
                     const float* __restrict__ scale,
                     float* __restrict__ out)
{
    __shared__ float  sx[CIN][RPB + 2][34];   // halo tile
    __shared__ float  sth[CG][LPC];           // clipped theta
    __shared__ float  srm[CIN][RPB + 2];      // per-(ci,row) max (skip threshold)
    __shared__ float  tv[TABN + 1];           // exact f at grid points
    __shared__ float2 tab[TABN];              // (c0, c1): f ~= c1*d + c0 on interval i

    const int rt = blockIdx.x;       // row tile 0..7
    const int cg = blockIdx.y;       // cout group 0..15
    const int b  = blockIdx.z;       // batch
    const int y0 = rt * RPB;
    const int c0 = cg * CG;
    const int tid = threadIdx.x;

    // ---- build exact table values ----
    for (int i = tid; i <= TABN; i += NTHR) {
        tv[i] = ekv_exact(TD0 + (float)i * TH);
    }

    // ---- load x halo tile (zero-padded) ----
    for (int i = tid; i < CIN * (RPB + 2) * 34; i += NTHR) {
        int cc = i % 34;
        int r  = (i / 34) % (RPB + 2);
        int ci = i / (34 * (RPB + 2));
        int gy = y0 - 1 + r;
        int gx = cc - 1;
        float v = 0.0f;
        if (gy >= 0 && gy < HH && gx >= 0 && gx < WW)
            v = x[((b * CIN + ci) * HH + gy) * WW + gx];
        sx[ci][r][cc] = v;
    }
    // ---- load + clip theta for this cout group ----
    for (int i = tid; i < CG * LPC; i += NTHR) {
        int l = i % LPC;
        int c = i / LPC;
        float t = theta[(c0 + c) * LPC + l];
        sth[c][l] = fminf(fmaxf(t, 1.0f), 8.0f);
    }
    __syncthreads();

    // ---- convert table to absolute-form line coeffs: f = c1*d + c0 ----
    for (int i = tid; i < TABN; i += NTHR) {
        float f0 = tv[i], f1 = tv[i + 1];
        float c1 = (f1 - f0) * TINVH;
        float xi = TD0 + (float)i * TH;
        tab[i] = make_float2(fmaf(-c1, xi, f0), c1);
    }
    // ---- per-(ci,row) max over the 34-wide row ----
    if (tid < CIN * (RPB + 2)) {
        int r  = tid % (RPB + 2);
        int ci = tid / (RPB + 2);
        float m = -1e30f;
        #pragma unroll
        for (int cc = 0; cc < 34; cc++) m = fmaxf(m, sx[ci][r][cc]);
        srm[ci][r] = m;
    }
    __syncthreads();

    const int tx = tid & 31;    // output column
    const int ty = tid >> 5;    // output row within tile (warp id)

    float acc[CG];
    #pragma unroll
    for (int c = 0; c < CG; c++) acc[c] = 0.0f;

    const float DSKIP = 0.85f;           // term negligible when vg - th < -DSKIP
    const float TBIAS = -TD0 * TINVH;    // index = d*TINVH + TBIAS

    #pragma unroll 1
    for (int ci = 0; ci < CIN; ci++) {
        #pragma unroll 1
        for (int ky = 0; ky < 3; ky++) {
            const float vthr = srm[ci][ty + ky] + DSKIP;   // warp-uniform
            const float vg0 = sx[ci][ty + ky][tx + 0];
            const float vg1 = sx[ci][ty + ky][tx + 1];
            const float vg2 = sx[ci][ty + ky][tx + 2];
            const int lbase = ci * 9 + ky * 3;
            #pragma unroll
            for (int c = 0; c < CG; c++) {
                float th0 = sth[c][lbase + 0];
                float th1 = sth[c][lbase + 1];
                float th2 = sth[c][lbase + 2];
                if (th0 <= vthr) {
                    float d = fminf(fmaxf(vg0 - th0, TD0), TD1);
                    int idx = min(__float2int_rd(fmaf(d, TINVH, TBIAS)), TABN - 1);
                    float2 cc2 = tab[idx];
                    acc[c] += fmaf(cc2.y, d, cc2.x);
                }
                if (th1 <= vthr) {
                    float d = fminf(fmaxf(vg1 - th1, TD0), TD1);
                    int idx = min(__float2int_rd(fmaf(d, TINVH, TBIAS)), TABN - 1);
                    float2 cc2 = tab[idx];
                    acc[c] += fmaf(cc2.y, d, cc2.x);
                }
                if (th2 <= vthr) {
                    float d = fminf(fmaxf(vg2 - th2, TD0), TD1);
                    int idx = min(__float2int_rd(fmaf(d, TINVH, TBIAS)), TABN - 1);
                    float2 cc2 = tab[idx];
                    acc[c] += fmaf(cc2.y, d, cc2.x);
                }
            }
        }
    }

    const float sc = scale[0] * (0.05625f * 0.1f);   // ALPHA * R * scale
    const int y = y0 + ty;
    #pragma unroll
    for (int c = 0; c < CG; c++) {
        out[((b * COUTT + (c0 + c)) * HH + y) * WW + tx] = acc[c] * sc;
    }
}

extern "C" void kernel_launch(void* const* d_in, const int* in_sizes, int n_in,
                              void* d_out, int out_size) {
    const float* x     = (const float*)d_in[0];
    const float* theta = (const float*)d_in[1];
    const float* scale = (const float*)d_in[2];
    float* out = (float*)d_out;
    (void)in_sizes; (void)n_in; (void)out_size;

    dim3 grid(HH / RPB, COUTT / CG, BB);   // 8 x 16 x 8 = 1024 blocks
    dim3 block(NTHR);
    ekv_conv_kernel<<<grid, block>>>(x, theta, scale, out);
}

// round 4
// speedup vs baseline: 1.5908x; 1.0702x over previous
#include <cuda_runtime.h>

// EKVNonLinearConv via piecewise-linear table of f(d) = sp(min(a,20))^2 - sp(min(a-D,20))^2
//   a = d/0.075, D = 0.1/0.075. f == 0 exactly for d >= 1.6; negligible for d < -0.85.
//   out = ALPHA*R*scale * sum_l f(vg - th)
// Table built once by a tiny pre-kernel into a __device__ global; main kernel copies it to smem.
// Table extended past d=1.6 with exact-zero entries so the saturated region maps to f==0.

#define CIN    16
#define COUTT  64
#define HH     32
#define WW     32
#define BB     8
#define CG     4      // couts per block
#define RPB    8      // output rows per block
#define NTHR   256    // 8 warps, one output row per warp
#define LPC    144    // CIN*3*3

#define TABN   512               // live intervals covering [-0.96, 1.6]
#define TABEXT 516               // +4 zero entries for d >= 1.6 (even # of float2 for float4 copy)
#define TD0    (-0.96f)
#define TH     0.005f            // kinks d=1.5 -> gridpt 492, d=1.6 -> gridpt 512 (exact)
#define TINVH  200.0f
#define TBIAS  192.0f            // -TD0 * TINVH
#define TDMAX  1.601f            // clamp -> idx 512 (zero entry); f(d>=1.6) == 0 exactly

__device__ float2 g_tab[TABEXT]; // (c0, c1): f ~= c1*d + c0 on interval i

__device__ __forceinline__ float ekv_exact(float d) {
    const float INVD  = 13.333333333333334f;
    const float DELTA = 1.3333333333333333f;
    float a  = d * INVD;
    float a1 = fminf(fmaxf(a, -50.0f), 20.0f);
    float a2 = fminf(fmaxf(a - DELTA, -50.0f), 20.0f);
    float l1 = log1pf(expf(a1));
    float l2 = log1pf(expf(a2));
    return fmaf(l1, l1, -l2 * l2);
}

__global__ void build_table_kernel() {
    int i = blockIdx.x * blockDim.x + threadIdx.x;
    if (i < TABEXT) {
        float xi = TD0 + (float)i * TH;
        float f0 = ekv_exact(xi);
        float f1 = ekv_exact(xi + TH);
        float c1 = (f1 - f0) * TINVH;
        // entries i >= 512 give f0 = f1 = 0 -> (0,0): exact zero for saturated d
        g_tab[i] = make_float2(fmaf(-c1, xi, f0), c1);
    }
}

__global__ __launch_bounds__(NTHR)
void ekv_conv_kernel(const float* __restrict__ x,
                     const float* __restrict__ theta,
                     const float* __restrict__ scale,
                     float* __restrict__ out)
{
    __shared__ float  sx[CIN][RPB + 2][34];   // halo tile (21.75 KB)
    __shared__ float  sth[CG][LPC];           // clipped theta (2.25 KB)
    __shared__ float  srm[CIN][RPB + 2];      // per-(ci,row) max (skip threshold)
    __shared__ float2 tab[TABEXT];            // ~4 KB

    const int rt = blockIdx.x;       // row tile 0..3
    const int cg = blockIdx.y;       // cout group 0..15
    const int b  = blockIdx.z;       // batch
    const int y0 = rt * RPB;
    const int c0 = cg * CG;
    const int tid = threadIdx.x;

    // ---- copy table from global (L2-hot after first wave) ----
    {
        const float4* src = (const float4*)g_tab;
        float4*       dst = (float4*)tab;
        for (int i = tid; i < TABEXT / 2; i += NTHR) dst[i] = src[i];
    }

    // ---- load x halo tile (zero-padded) ----
    for (int i = tid; i < CIN * (RPB + 2) * 34; i += NTHR) {
        int cc = i % 34;
        int r  = (i / 34) % (RPB + 2);
        int ci = i / (34 * (RPB + 2));
        int gy = y0 - 1 + r;
        int gx = cc - 1;
        float v = 0.0f;
        if (gy >= 0 && gy < HH && gx >= 0 && gx < WW)
            v = x[((b * CIN + ci) * HH + gy) * WW + gx];
        sx[ci][r][cc] = v;
    }
    // ---- load + clip theta for this cout group ----
    for (int i = tid; i < CG * LPC; i += NTHR) {
        int l = i % LPC;
        int c = i / LPC;
        float t = theta[(c0 + c) * LPC + l];
        sth[c][l] = fminf(fmaxf(t, 1.0f), 8.0f);
    }
    __syncthreads();

    // ---- per-(ci,row) max over the 34-wide row (skip bound) ----
    if (tid < CIN * (RPB + 2)) {
        int r  = tid % (RPB + 2);
        int ci = tid / (RPB + 2);
        float m = -1e30f;
        #pragma unroll
        for (int cc = 0; cc < 34; cc++) m = fmaxf(m, sx[ci][r][cc]);
        srm[ci][r] = m;
    }
    __syncthreads();

    const int tx = tid & 31;    // output column
    const int ty = tid >> 5;    // output row within tile (warp id 0..7)

    float acc[CG];
    #pragma unroll
    for (int c = 0; c < CG; c++) acc[c] = 0.0f;

    const float DSKIP = 0.85f;   // term negligible when vg - th < -DSKIP

    #pragma unroll 1
    for (int ci = 0; ci < CIN; ci++) {
        #pragma unroll 1
        for (int ky = 0; ky < 3; ky++) {
            const float vthr = srm[ci][ty + ky] + DSKIP;   // warp-uniform
            const float vg0 = sx[ci][ty + ky][tx + 0];
            const float vg1 = sx[ci][ty + ky][tx + 1];
            const float vg2 = sx[ci][ty + ky][tx + 2];
            const int lbase = ci * 9 + ky * 3;
            #pragma unroll
            for (int c = 0; c < CG; c++) {
                float th0 = sth[c][lbase + 0];
                float th1 = sth[c][lbase + 1];
                float th2 = sth[c][lbase + 2];
                if (th0 <= vthr) {
                    float d = fminf(fmaxf(vg0 - th0, TD0), TDMAX);
                    int idx = __float2int_rd(fmaf(d, TINVH, TBIAS));
                    float2 cc2 = tab[idx];
                    acc[c] += fmaf(cc2.y, d, cc2.x);
                }
                if (th1 <= vthr) {
                    float d = fminf(fmaxf(vg1 - th1, TD0), TDMAX);
                    int idx = __float2int_rd(fmaf(d, TINVH, TBIAS));
                    float2 cc2 = tab[idx];
                    acc[c] += fmaf(cc2.y, d, cc2.x);
                }
                if (th2 <= vthr) {
                    float d = fminf(fmaxf(vg2 - th2, TD0), TDMAX);
                    int idx = __float2int_rd(fmaf(d, TINVH, TBIAS));
                    float2 cc2 = tab[idx];
                    acc[c] += fmaf(cc2.y, d, cc2.x);
                }
            }
        }
    }

    const float sc = scale[0] * (0.05625f * 0.1f);   // ALPHA * R * scale
    const int y = y0 + ty;
    #pragma unroll
    for (int c = 0; c < CG; c++) {
        out[((b * COUTT + (c0 + c)) * HH + y) * WW + tx] = acc[c] * sc;
    }
}

extern "C" void kernel_launch(void* const* d_in, const int* in_sizes, int n_in,
                              void* d_out, int out_size) {
    const float* x     = (const float*)d_in[0];
    const float* theta = (const float*)d_in[1];
    const float* scale = (const float*)d_in[2];
    float* out = (float*)d_out;
    (void)in_sizes; (void)n_in; (void)out_size;

    build_table_kernel<<<3, 256>>>();

    dim3 grid(HH / RPB, COUTT / CG, BB);   // 4 x 16 x 8 = 512 blocks
    dim3 block(NTHR);
    ekv_conv_kernel<<<grid, block>>>(x, theta, scale, out);
}